// round 7
// baseline (speedup 1.0000x reference)
#include <cuda_runtime.h>

#define NLAB   2047
#define NBATCH 2048

// Precomputed EXP of compact transition tables (gathered per launch, deterministic).
// eTup[n] = exp(transitions[parent(n), n, :, :])  (message n -> parent)
// eTdn[n] = exp(transitions[n, parent(n), :, :])  (message parent -> n)
__device__ float4 g_eTup[2048];
__device__ float4 g_eTdn[2048];

__global__ void prep_kernel(const float* __restrict__ trans) {
    int n = blockIdx.x * blockDim.x + threadIdx.x;
    if (n >= NLAB) return;
    if (n == 0) {
        g_eTup[0] = make_float4(1.f, 1.f, 1.f, 1.f);
        g_eTdn[0] = make_float4(1.f, 1.f, 1.f, 1.f);
        return;
    }
    int p = (n - 1) >> 1;
    const float4* t4 = reinterpret_cast<const float4*>(trans);
    float4 u = t4[(size_t)p * NLAB + n];   // dst=parent, src=n
    float4 d = t4[(size_t)n * NLAB + p];   // dst=n, src=parent
    g_eTup[n] = make_float4(__expf(u.x), __expf(u.y), __expf(u.z), __expf(u.w));
    g_eTdn[n] = make_float4(__expf(d.x), __expf(d.y), __expf(d.z), __expf(d.w));
}

// Both-destination-class logsumexp for one edge, sharing one exp.
__device__ __forceinline__ float2 lsepair2(float2 x, float4 eT) {
    float m  = fmaxf(x.x, x.y);
    float pd = __expf(fminf(x.x, x.y) - m);
    bool  f  = (x.x >= x.y);
    float a0 = f ? eT.x : eT.y, b0 = f ? eT.y : eT.x;
    float a1 = f ? eT.z : eT.w, b1 = f ? eT.w : eT.z;
    return make_float2(m + __logf(fmaf(pd, b0, a0)),
                       m + __logf(fmaf(pd, b1, a1)));
}

__device__ __forceinline__ float2 up_combine(float2 xl, float2 xr, float4 Tl, float4 Tr) {
    float2 a = lsepair2(xl, Tl);
    float2 b = lsepair2(xr, Tr);
    return make_float2(a.x + b.x, a.y + b.y);
}

__device__ __forceinline__ float2 f2add(float2 a, float2 b) {
    return make_float2(a.x + b.x, a.y + b.y);
}

__device__ __forceinline__ float lse2(float u, float v) {
    float m = fmaxf(u, v);
    return m + __logf(1.0f + __expf(fminf(u, v) - m));
}

__device__ __forceinline__ void emit2(float* __restrict__ orow, int n, float2 s) {
    float z = lse2(s.x, s.y);
    orow[n]        = s.x - z;
    orow[NLAB + n] = s.y - z;
}

__device__ __forceinline__ float2 ld_e(const float* __restrict__ er, int n) {
    return make_float2(er[n], er[NLAB + n]);
}

// One batch row per 64-thread CTA. Lane tid owns L6 node 63+tid and its whole
// subtree (L7..leaves) privately. Top 63 nodes (L0..L5) handled by warp 0 with
// __syncwarp only. Exactly 2 block barriers.
// smem ~8KB/CTA -> 14 CTAs/SM; grid 2048 -> ~13.8 CTAs/SM, near-perfect balance.
__global__ void __launch_bounds__(64, 14) crf_kernel(const float* __restrict__ em,
                                                     float* __restrict__ out) {
    // x = e + alpha per node. X[j][lane]: lane-private nodes, level-major
    // (j uniform per instruction -> conflict-free). j: 0-1=L7, 2-5=L8, 6-13=L9.
    __shared__ float2 X[14][64];
    __shared__ float2 S6[64];                 // x (then unchanged) at L6 nodes
    __shared__ float2 S5[32], S4[16], S3[8], S2[4], S1[2], S0[1];  // x, then t

    const int tid = threadIdx.x;
    const size_t boff = (size_t)blockIdx.x * (2 * NLAB);
    const float* __restrict__ er = em + boff;
    float* __restrict__ orow = out + boff;

    const int h  = 64 + tid;      // 1-based heap index of owned L6 node
    const int B6 = h - 1;         // 63 + tid
    const int B7 = 2 * h - 1;
    const int B8 = 4 * h - 1;
    const int B9 = 8 * h - 1;
    const int BL = 16 * h - 1;    // first of 16 leaves

    // ================= private UP (all 64 lanes, no sync) =================
    #pragma unroll
    for (int j = 0; j < 8; j++) {             // L9 from leaf pairs
        int n = B9 + j, k = BL + 2 * j;
        float2 a = up_combine(ld_e(er, k), ld_e(er, k + 1), g_eTup[k], g_eTup[k + 1]);
        X[6 + j][tid] = f2add(ld_e(er, n), a);
    }
    #pragma unroll
    for (int j = 0; j < 4; j++) {             // L8
        int n = B8 + j, c = B9 + 2 * j;
        float2 a = up_combine(X[6 + 2 * j][tid], X[7 + 2 * j][tid], g_eTup[c], g_eTup[c + 1]);
        X[2 + j][tid] = f2add(ld_e(er, n), a);
    }
    #pragma unroll
    for (int j = 0; j < 2; j++) {             // L7
        int n = B7 + j, c = B8 + 2 * j;
        float2 a = up_combine(X[2 + 2 * j][tid], X[3 + 2 * j][tid], g_eTup[c], g_eTup[c + 1]);
        X[j][tid] = f2add(ld_e(er, n), a);
    }
    {                                          // L6 -> S6
        float2 a = up_combine(X[0][tid], X[1][tid], g_eTup[B7], g_eTup[B7 + 1]);
        S6[tid] = f2add(ld_e(er, B6), a);
    }
    __syncthreads();   // barrier #1: S6 complete from both warps

    // ================= top of tree: warp 0 only, syncwarp =================
    if (tid < 32) {
        {                                      // L5 up
            int n = 31 + tid, c = 63 + 2 * tid;
            float2 a = up_combine(S6[2 * tid], S6[2 * tid + 1], g_eTup[c], g_eTup[c + 1]);
            S5[tid] = f2add(ld_e(er, n), a);
        }
        __syncwarp();
        if (tid < 16) {                        // L4 up
            int n = 15 + tid, c = 31 + 2 * tid;
            float2 a = up_combine(S5[2 * tid], S5[2 * tid + 1], g_eTup[c], g_eTup[c + 1]);
            S4[tid] = f2add(ld_e(er, n), a);
        }
        __syncwarp();
        if (tid < 8) {                         // L3 up
            int n = 7 + tid, c = 15 + 2 * tid;
            float2 a = up_combine(S4[2 * tid], S4[2 * tid + 1], g_eTup[c], g_eTup[c + 1]);
            S3[tid] = f2add(ld_e(er, n), a);
        }
        __syncwarp();
        if (tid < 4) {                         // L2 up
            int n = 3 + tid, c = 7 + 2 * tid;
            float2 a = up_combine(S3[2 * tid], S3[2 * tid + 1], g_eTup[c], g_eTup[c + 1]);
            S2[tid] = f2add(ld_e(er, n), a);
        }
        __syncwarp();
        if (tid < 2) {                         // L1 up
            int n = 1 + tid, c = 3 + 2 * tid;
            float2 a = up_combine(S2[2 * tid], S2[2 * tid + 1], g_eTup[c], g_eTup[c + 1]);
            S1[tid] = f2add(ld_e(er, n), a);
        }
        __syncwarp();
        if (tid == 0) {                        // root: emit, t0 = e0
            float2 a  = up_combine(S1[0], S1[1], g_eTup[1], g_eTup[2]);
            float2 x0 = f2add(ld_e(er, 0), a);
            emit2(orow, 0, x0);
            S0[0] = ld_e(er, 0);
        }
        __syncwarp();
        if (tid < 2) {                         // L1 down (S* arrays: x -> t)
            int n = 1 + tid;
            float2 be = lsepair2(S0[0], g_eTdn[n]);
            emit2(orow, n, f2add(S1[tid], be));
            S1[tid] = f2add(ld_e(er, n), be);
        }
        __syncwarp();
        if (tid < 4) {                         // L2 down
            int n = 3 + tid;
            float2 be = lsepair2(S1[tid >> 1], g_eTdn[n]);
            emit2(orow, n, f2add(S2[tid], be));
            S2[tid] = f2add(ld_e(er, n), be);
        }
        __syncwarp();
        if (tid < 8) {                         // L3 down
            int n = 7 + tid;
            float2 be = lsepair2(S2[tid >> 1], g_eTdn[n]);
            emit2(orow, n, f2add(S3[tid], be));
            S3[tid] = f2add(ld_e(er, n), be);
        }
        __syncwarp();
        if (tid < 16) {                        // L4 down
            int n = 15 + tid;
            float2 be = lsepair2(S3[tid >> 1], g_eTdn[n]);
            emit2(orow, n, f2add(S4[tid], be));
            S4[tid] = f2add(ld_e(er, n), be);
        }
        __syncwarp();
        {                                      // L5 down (all 32 lanes)
            int n = 31 + tid;
            float2 be = lsepair2(S4[tid >> 1], g_eTdn[n]);
            emit2(orow, n, f2add(S5[tid], be));
            S5[tid] = f2add(ld_e(er, n), be);
        }
    }
    __syncthreads();   // barrier #2: t at L5 ready for both warps

    // ================= private DOWN (all 64 lanes, depth-first) ===========
    float2 t6;
    {
        float2 be = lsepair2(S5[tid >> 1], g_eTdn[B6]);
        emit2(orow, B6, f2add(S6[tid], be));
        t6 = f2add(ld_e(er, B6), be);
    }
    #pragma unroll
    for (int j7 = 0; j7 < 2; j7++) {
        int n7 = B7 + j7;
        float2 be7 = lsepair2(t6, g_eTdn[n7]);
        emit2(orow, n7, f2add(X[j7][tid], be7));
        float2 t7 = f2add(ld_e(er, n7), be7);
        #pragma unroll
        for (int j8 = 0; j8 < 2; j8++) {
            int i8 = 2 * j7 + j8, n8 = B8 + i8;
            float2 be8 = lsepair2(t7, g_eTdn[n8]);
            emit2(orow, n8, f2add(X[2 + i8][tid], be8));
            float2 t8 = f2add(ld_e(er, n8), be8);
            #pragma unroll
            for (int j9 = 0; j9 < 2; j9++) {
                int i9 = 2 * i8 + j9, n9 = B9 + i9;
                float2 be9 = lsepair2(t8, g_eTdn[n9]);
                emit2(orow, n9, f2add(X[6 + i9][tid], be9));
                float2 t9 = f2add(ld_e(er, n9), be9);
                int k = BL + 2 * i9;
                float2 bl = lsepair2(t9, g_eTdn[k]);
                emit2(orow, k, f2add(ld_e(er, k), bl));          // leaf: alpha=0
                float2 br = lsepair2(t9, g_eTdn[k + 1]);
                emit2(orow, k + 1, f2add(ld_e(er, k + 1), br));
            }
        }
    }
}

extern "C" void kernel_launch(void* const* d_in, const int* in_sizes, int n_in,
                              void* d_out, int out_size) {
    const float* em = (const float*)d_in[0];
    const float* tr = (const float*)d_in[1];
    if (n_in >= 2 && in_sizes[0] != NBATCH * 2 * NLAB) {
        em = (const float*)d_in[1];
        tr = (const float*)d_in[0];
    }
    prep_kernel<<<(NLAB + 255) / 256, 256>>>(tr);
    crf_kernel<<<NBATCH, 64>>>(em, (float*)d_out);
}

// round 8
// speedup vs baseline: 1.8170x; 1.8170x over previous
#include <cuda_runtime.h>

#define NLAB   2047
#define NBATCH 2048

// Precomputed EXP of compact transition tables (gathered per launch, deterministic).
// eTup[n] = exp(transitions[parent(n), n, :, :])  (message n -> parent)
// eTdn[n] = exp(transitions[n, parent(n), :, :])  (message parent -> n)
__device__ float4 g_eTup[2048];
__device__ float4 g_eTdn[2048];

__global__ void prep_kernel(const float* __restrict__ trans) {
    int n = blockIdx.x * blockDim.x + threadIdx.x;
    if (n >= NLAB) return;
    if (n == 0) {
        g_eTup[0] = make_float4(1.f, 1.f, 1.f, 1.f);
        g_eTdn[0] = make_float4(1.f, 1.f, 1.f, 1.f);
        return;
    }
    int p = (n - 1) >> 1;
    const float4* t4 = reinterpret_cast<const float4*>(trans);
    float4 u = t4[(size_t)p * NLAB + n];   // dst=parent, src=n
    float4 d = t4[(size_t)n * NLAB + p];   // dst=n, src=parent
    g_eTup[n] = make_float4(__expf(u.x), __expf(u.y), __expf(u.z), __expf(u.w));
    g_eTdn[n] = make_float4(__expf(d.x), __expf(d.y), __expf(d.z), __expf(d.w));
}

// Both-destination-class logsumexp for one edge, sharing one exp.
__device__ __forceinline__ float2 lsepair2(float2 x, float4 eT) {
    float m  = fmaxf(x.x, x.y);
    float pd = __expf(fminf(x.x, x.y) - m);
    bool  f  = (x.x >= x.y);
    float a0 = f ? eT.x : eT.y, b0 = f ? eT.y : eT.x;
    float a1 = f ? eT.z : eT.w, b1 = f ? eT.w : eT.z;
    return make_float2(m + __logf(fmaf(pd, b0, a0)),
                       m + __logf(fmaf(pd, b1, a1)));
}

__device__ __forceinline__ float2 up_combine(float2 xl, float2 xr, float4 Tl, float4 Tr) {
    float2 a = lsepair2(xl, Tl);
    float2 b = lsepair2(xr, Tr);
    return make_float2(a.x + b.x, a.y + b.y);
}

__device__ __forceinline__ float2 f2add(float2 a, float2 b) {
    return make_float2(a.x + b.x, a.y + b.y);
}

__device__ __forceinline__ float lse2(float u, float v) {
    float m = fmaxf(u, v);
    return m + __logf(1.0f + __expf(fminf(u, v) - m));
}

__device__ __forceinline__ void emit2(float* __restrict__ orow, int n, float2 s) {
    float z = lse2(s.x, s.y);
    orow[n]        = s.x - z;
    orow[NLAB + n] = s.y - z;
}

__device__ __forceinline__ float2 ld_e(const float* __restrict__ er, int n) {
    return make_float2(er[n], er[NLAB + n]);
}

// beta contribution to both children of a parent with final t=tp (shared exp).
#define PARENT_EXP(tp, m, pd, f) \
    float m  = fmaxf((tp).x, (tp).y); \
    float pd = __expf(fminf((tp).x, (tp).y) - m); \
    bool  f  = ((tp).x >= (tp).y);

__device__ __forceinline__ float2 child_be(float m, float pd, bool f, float4 eT) {
    float a0 = f ? eT.x : eT.y, b0 = f ? eT.y : eT.x;
    float a1 = f ? eT.z : eT.w, b1 = f ? eT.w : eT.z;
    return make_float2(m + __logf(fmaf(pd, b0, a0)),
                       m + __logf(fmaf(pd, b1, a1)));
}

// TWO rows per 256-thread CTA; 6 block barriers total.
// Et/At: E (becomes t on the way down) and alpha for nodes 0..510.
// E9/A9: emission/alpha for L9 nodes, stored [j][i] so the SAME thread that
// wrote them in the fused up phase reads them in the fused down phase
// (conflict-free, lane-consecutive).
__global__ void __launch_bounds__(256) crf_kernel(const float* __restrict__ em,
                                                  float* __restrict__ out) {
    __shared__ float2 Et[2][512], At[2][512];
    __shared__ float2 E9[2][2][256], A9[2][2][256];
    __shared__ float2 S5[2][32], S4[2][16], S3[2][8], S2[2][4], S1[2][2], S0[2];

    const int tid = threadIdx.x;
    const size_t b0 = (size_t)(2 * blockIdx.x) * (2 * NLAB);

    // ============ phase 1: fused private up  leaves -> L9 -> L8 ============
    #pragma unroll
    for (int r = 0; r < 2; ++r) {
        const float* __restrict__ er = em + b0 + (size_t)r * (2 * NLAB);
        if (tid < 255) Et[r][tid] = ld_e(er, tid);   // top emissions, coalesced
        const int i  = tid;
        const int k0 = 1023 + 4 * i;                 // 4 leaves, consecutive
        const int nl = 511 + 2 * i;                  // L9 pair
        float2 aL = up_combine(ld_e(er, k0),     ld_e(er, k0 + 1),
                               g_eTup[k0],       g_eTup[k0 + 1]);
        float2 aR = up_combine(ld_e(er, k0 + 2), ld_e(er, k0 + 3),
                               g_eTup[k0 + 2],   g_eTup[k0 + 3]);
        float2 enl = ld_e(er, nl), enr = ld_e(er, nl + 1);
        E9[r][0][i] = enl; A9[r][0][i] = aL;
        E9[r][1][i] = enr; A9[r][1][i] = aR;
        float2 a8 = up_combine(f2add(enl, aL), f2add(enr, aR),
                               g_eTup[nl], g_eTup[nl + 1]);
        const int p8 = 255 + i;
        Et[r][p8] = ld_e(er, p8);
        At[r][p8] = a8;
    }
    __syncthreads();                                               // barrier 1

    // ============ phase 2: up L7 (rows split across thread halves) =========
    {
        int r = tid >> 7, k = tid & 127;
        int p = 127 + k, c = 255 + 2 * k;
        At[r][p] = up_combine(f2add(Et[r][c], At[r][c]),
                              f2add(Et[r][c + 1], At[r][c + 1]),
                              g_eTup[c], g_eTup[c + 1]);
    }
    __syncthreads();                                               // barrier 2

    // ============ phase 3: up L6 =========
    if (tid < 128) {
        int r = tid >> 6, k = tid & 63;
        int p = 63 + k, c = 127 + 2 * k;
        At[r][p] = up_combine(f2add(Et[r][c], At[r][c]),
                              f2add(Et[r][c + 1], At[r][c + 1]),
                              g_eTup[c], g_eTup[c + 1]);
    }
    __syncthreads();                                               // barrier 3

    // ============ phase 4: top of tree, warp r handles row r ==============
    if (tid < 64) {
        const int r = tid >> 5, lane = tid & 31;
        const float* __restrict__ er = em + b0 + (size_t)r * (2 * NLAB);
        float* __restrict__ orow = out + b0 + (size_t)r * (2 * NLAB);

        // L5 up
        const int n5 = 31 + lane, c5 = 63 + 2 * lane;
        float2 e5 = ld_e(er, n5);
        float2 x5 = f2add(e5, up_combine(f2add(Et[r][c5], At[r][c5]),
                                         f2add(Et[r][c5 + 1], At[r][c5 + 1]),
                                         g_eTup[c5], g_eTup[c5 + 1]));
        S5[r][lane] = x5;
        __syncwarp();
        float2 e4, x4;
        if (lane < 16) {
            int n = 15 + lane, c = 31 + 2 * lane;
            e4 = ld_e(er, n);
            x4 = f2add(e4, up_combine(S5[r][2 * lane], S5[r][2 * lane + 1],
                                      g_eTup[c], g_eTup[c + 1]));
            S4[r][lane] = x4;
        }
        __syncwarp();
        float2 e3, x3;
        if (lane < 8) {
            int n = 7 + lane, c = 15 + 2 * lane;
            e3 = ld_e(er, n);
            x3 = f2add(e3, up_combine(S4[r][2 * lane], S4[r][2 * lane + 1],
                                      g_eTup[c], g_eTup[c + 1]));
            S3[r][lane] = x3;
        }
        __syncwarp();
        float2 e2v, x2v;
        if (lane < 4) {
            int n = 3 + lane, c = 7 + 2 * lane;
            e2v = ld_e(er, n);
            x2v = f2add(e2v, up_combine(S3[r][2 * lane], S3[r][2 * lane + 1],
                                        g_eTup[c], g_eTup[c + 1]));
            S2[r][lane] = x2v;
        }
        __syncwarp();
        float2 e1v, x1v;
        if (lane < 2) {
            int n = 1 + lane, c = 3 + 2 * lane;
            e1v = ld_e(er, n);
            x1v = f2add(e1v, up_combine(S2[r][2 * lane], S2[r][2 * lane + 1],
                                        g_eTup[c], g_eTup[c + 1]));
            S1[r][lane] = x1v;
        }
        __syncwarp();
        if (lane == 0) {
            float2 e0v = ld_e(er, 0);
            float2 x0 = f2add(e0v, up_combine(S1[r][0], S1[r][1],
                                              g_eTup[1], g_eTup[2]));
            emit2(orow, 0, x0);
            S0[r] = e0v;                       // t at root = e (beta = 0)
        }
        __syncwarp();
        // down; S-arrays flip from x to t level by level
        if (lane < 2) {
            int n = 1 + lane;
            float2 be = lsepair2(S0[r], g_eTdn[n]);
            emit2(orow, n, f2add(x1v, be));
            S1[r][lane] = f2add(e1v, be);
        }
        __syncwarp();
        if (lane < 4) {
            int n = 3 + lane;
            float2 be = lsepair2(S1[r][lane >> 1], g_eTdn[n]);
            emit2(orow, n, f2add(x2v, be));
            S2[r][lane] = f2add(e2v, be);
        }
        __syncwarp();
        if (lane < 8) {
            int n = 7 + lane;
            float2 be = lsepair2(S2[r][lane >> 1], g_eTdn[n]);
            emit2(orow, n, f2add(x3, be));
            S3[r][lane] = f2add(e3, be);
        }
        __syncwarp();
        if (lane < 16) {
            int n = 15 + lane;
            float2 be = lsepair2(S3[r][lane >> 1], g_eTdn[n]);
            emit2(orow, n, f2add(x4, be));
            S4[r][lane] = f2add(e4, be);
        }
        __syncwarp();
        {   // L5 down + L6 down (t written into Et in place)
            int n = 31 + lane;
            float2 be = lsepair2(S4[r][lane >> 1], g_eTdn[n]);
            emit2(orow, n, f2add(x5, be));
            float2 t5 = f2add(e5, be);
            PARENT_EXP(t5, m, pd, f)
            #pragma unroll
            for (int j = 0; j < 2; ++j) {
                int n6 = 63 + 2 * lane + j;
                float2 be6 = child_be(m, pd, f, g_eTdn[n6]);
                float2 E = Et[r][n6];
                emit2(orow, n6, f2add(f2add(E, At[r][n6]), be6));
                Et[r][n6] = f2add(E, be6);     // t6
            }
        }
    }
    __syncthreads();                                               // barrier 4

    // ============ phase 5: down L6 parents -> t[L7] =======================
    if (tid < 128) {
        int r = tid >> 6, k = tid & 63;
        float* __restrict__ orow = out + b0 + (size_t)r * (2 * NLAB);
        float2 tp = Et[r][63 + k];
        PARENT_EXP(tp, m, pd, f)
        #pragma unroll
        for (int j = 0; j < 2; ++j) {
            int n = 127 + 2 * k + j;
            float2 be = child_be(m, pd, f, g_eTdn[n]);
            float2 E = Et[r][n];
            emit2(orow, n, f2add(f2add(E, At[r][n]), be));
            Et[r][n] = f2add(E, be);
        }
    }
    __syncthreads();                                               // barrier 5

    // ============ phase 6: down L7 parents -> t[L8] =======================
    {
        int r = tid >> 7, k = tid & 127;
        float* __restrict__ orow = out + b0 + (size_t)r * (2 * NLAB);
        float2 tp = Et[r][127 + k];
        PARENT_EXP(tp, m, pd, f)
        #pragma unroll
        for (int j = 0; j < 2; ++j) {
            int n = 255 + 2 * k + j;
            float2 be = child_be(m, pd, f, g_eTdn[n]);
            float2 E = Et[r][n];
            emit2(orow, n, f2add(f2add(E, At[r][n]), be));
            Et[r][n] = f2add(E, be);
        }
    }
    __syncthreads();                                               // barrier 6

    // ============ phase 7: fused private down  L8 -> L9 -> leaves =========
    #pragma unroll
    for (int r = 0; r < 2; ++r) {
        const float* __restrict__ er = em + b0 + (size_t)r * (2 * NLAB);
        float* __restrict__ orow = out + b0 + (size_t)r * (2 * NLAB);
        const int i = tid;
        float2 tp = Et[r][255 + i];
        PARENT_EXP(tp, m, pd, f)
        #pragma unroll
        for (int j = 0; j < 2; ++j) {
            int n9 = 511 + 2 * i + j;
            float2 be9 = child_be(m, pd, f, g_eTdn[n9]);
            float2 E = E9[r][j][i];
            emit2(orow, n9, f2add(f2add(E, A9[r][j][i]), be9));
            float2 t9 = f2add(E, be9);
            PARENT_EXP(t9, m9, pd9, f9)
            int k0 = 1023 + 4 * i + 2 * j;
            #pragma unroll
            for (int jj = 0; jj < 2; ++jj) {
                int kk = k0 + jj;
                float2 bl = child_be(m9, pd9, f9, g_eTdn[kk]);
                emit2(orow, kk, f2add(ld_e(er, kk), bl));   // leaf alpha = 0
            }
        }
    }
}

extern "C" void kernel_launch(void* const* d_in, const int* in_sizes, int n_in,
                              void* d_out, int out_size) {
    const float* em = (const float*)d_in[0];
    const float* tr = (const float*)d_in[1];
    if (n_in >= 2 && in_sizes[0] != NBATCH * 2 * NLAB) {
        em = (const float*)d_in[1];
        tr = (const float*)d_in[0];
    }
    prep_kernel<<<(NLAB + 255) / 256, 256>>>(tr);
    crf_kernel<<<NBATCH / 2, 256>>>(em, (float*)d_out);
}